// round 1
// baseline (speedup 1.0000x reference)
#include <cuda_runtime.h>
#include <cuda_bf16.h>
#include <cstdint>

// Problem constants
#define NB   8
#define CC   256
#define HH   50
#define WW   68
#define HW   (HH*WW)           // 3400
#define NR   4000
#define SCALE 0.0625f
#define ROWSTRIDE (WW*CC)      // 17408 floats per y-row in NHWC

// NHWC scratch: 8*3400*256 floats = 27.85 MB (static device global, allocation-free)
__device__ float g_nhwc[NB * HW * CC];

// ---------------------------------------------------------------------------
// Kernel 1: NCHW -> NHWC transpose. Per batch b: transpose [C=256][HW=3400]
// matrix. 32x32 smem tiles, coalesced on both sides.
// ---------------------------------------------------------------------------
__global__ __launch_bounds__(1024) void nchw_to_nhwc(const float* __restrict__ in) {
    __shared__ float tile[32][33];
    int b  = blockIdx.z;
    int p0 = blockIdx.x * 32;   // spatial (y*W+x) tile base, 0..3399
    int c0 = blockIdx.y * 32;   // channel tile base, 0..255

    int p = p0 + threadIdx.x;
    int c = c0 + threadIdx.y;
    if (p < HW)
        tile[threadIdx.y][threadIdx.x] = in[((size_t)b * CC + c) * HW + p];
    __syncthreads();

    int pp = p0 + threadIdx.y;
    int ccx = c0 + threadIdx.x;
    if (pp < HW)
        g_nhwc[((size_t)b * HW + pp) * CC + ccx] = tile[threadIdx.x][threadIdx.y];
}

// ---------------------------------------------------------------------------
// Kernel 2: RoIAlign (aligned avg, 8x8 sample grid -> 7x7 via 2x2 average).
// One CTA per roi, one thread per channel. All gathers are warp-coalesced
// 128B lines out of NHWC (L2-resident). Output staged in smem so the final
// 49KB-per-roi store is fully linear/coalesced.
// smem layout: s_out[c*49 + bin]  (stride 49 is odd -> conflict-free writes;
// final linear copy is trivially conflict-free).
// ---------------------------------------------------------------------------
__global__ __launch_bounds__(256) void roi_align_kernel(
    const float* __restrict__ rois, float* __restrict__ out)
{
    extern __shared__ float s_out[];   // 256*49 floats = 50176 B

    const int r = blockIdx.x;
    const int c = threadIdx.x;

    // Broadcast roi params (all threads read the same 5 floats: L1/L2 hit)
    const float* roi = rois + r * 5;
    const int   bi = (int)roi[0];
    const float x1 = roi[1] * SCALE;
    const float y1 = roi[2] * SCALE;
    const float x2 = roi[3] * SCALE;
    const float y2 = roi[4] * SCALE;
    const float roi_w = fmaxf(x2 - x1, 0.0f);
    const float roi_h = fmaxf(y2 - y1, 0.0f);
    const float bin_w = roi_w / 7.0f;
    const float bin_h = roi_h / 7.0f;

    // Precompute x-axis geometry for the 8 sample columns
    int   xoff[8];   // x0 * C  (element offset into a row)
    float lxv[8];    // fractional x
    float mxv[8];    // in-bounds mask (as float)
    #pragma unroll
    for (int pw = 0; pw < 8; pw++) {
        float w  = x1 + (float)pw * bin_w;
        mxv[pw]  = (w >= 0.0f && w < (float)WW) ? 1.0f : 0.0f;
        float xf = fminf(fmaxf(floorf(w), 0.0f), (float)(WW - 2));
        lxv[pw]  = w - xf;
        xoff[pw] = (int)xf * CC;
    }

    const float* fbase = g_nhwc + (size_t)bi * HW * CC + c;

    float prev[8];
    #pragma unroll
    for (int sph = 0; sph < 8; sph++) {
        float h  = y1 + (float)sph * bin_h;
        float my = (h >= 0.0f && h < (float)HH) ? 1.0f : 0.0f;
        float yf = fminf(fmaxf(floorf(h), 0.0f), (float)(HH - 2));
        float ly = h - yf;
        const float* r0 = fbase + (int)yf * ROWSTRIDE;
        const float* r1 = r0 + ROWSTRIDE;

        float s[8];
        #pragma unroll
        for (int pw = 0; pw < 8; pw++) {
            float v00 = __ldg(r0 + xoff[pw]);
            float v01 = __ldg(r0 + xoff[pw] + CC);
            float v10 = __ldg(r1 + xoff[pw]);
            float v11 = __ldg(r1 + xoff[pw] + CC);
            float top = fmaf(lxv[pw], v01 - v00, v00);
            float bot = fmaf(lxv[pw], v11 - v10, v10);
            float val = fmaf(ly, bot - top, top);
            s[pw] = val * (my * mxv[pw]);
        }

        if (sph > 0) {
            #pragma unroll
            for (int pw = 0; pw < 7; pw++) {
                s_out[c * 49 + (sph - 1) * 7 + pw] =
                    0.25f * ((prev[pw] + prev[pw + 1]) + (s[pw] + s[pw + 1]));
            }
        }
        #pragma unroll
        for (int pw = 0; pw < 8; pw++) prev[pw] = s[pw];
    }

    __syncthreads();

    // Coalesced linear store of the whole roi tile (256*49 floats contiguous)
    float* o = out + (size_t)r * (CC * 49);
    #pragma unroll
    for (int j = c; j < CC * 49; j += 256) {
        o[j] = s_out[j];
    }
}

// ---------------------------------------------------------------------------
extern "C" void kernel_launch(void* const* d_in, const int* in_sizes, int n_in,
                              void* d_out, int out_size)
{
    const float* features = (const float*)d_in[0];  // [8,256,50,68]
    const float* rois     = (const float*)d_in[1];  // [4000,5]
    float*       out      = (float*)d_out;          // [4000,256,7,7]

    // Transpose NCHW -> NHWC scratch
    dim3 tb(32, 32);
    dim3 tg((HW + 31) / 32, CC / 32, NB);
    nchw_to_nhwc<<<tg, tb>>>(features);

    // Main gather kernel: 50176B dynamic smem (> 48KB static limit)
    static const size_t smem_bytes = (size_t)CC * 49 * sizeof(float);
    cudaFuncSetAttribute(roi_align_kernel,
                         cudaFuncAttributeMaxDynamicSharedMemorySize,
                         (int)smem_bytes);
    roi_align_kernel<<<NR, CC, smem_bytes>>>(rois, out);
}